// round 17
// baseline (speedup 1.0000x reference)
#include <cuda_runtime.h>
#include <cuda_bf16.h>
#include <cstdint>

#define BB 64
#define TT 512
#define II 512
#define HH 1024
#define NCTA_DIR 64

// ---------------- scratch (device globals) ----------------------------------
__device__ float g_Xrz[2][TT][BB][2 * HH];
__device__ float g_Xh [2][TT][BB][HH];
__device__ float g_hm [2][2][BB][HH];          // master h, double-buffered [parity]
__device__ float g_Z  [2][BB][HH];
// A-operand fragments: [parity][dir][m-tile(4)][q(64)][split(2)][lane(32)]
__device__ uint4 g_hf[2][2][4][64][2][32];
__device__ uint4 g_Rf[2][4][64][2][32];
__device__ uint4 g_Wf[2][3][128][32][32];      // x-weight B-fragments (prep)
// data-ready flags, 32B padded; ALWAYS 0 at kernel entry (reset at kernel exit)
__device__ unsigned g_hflag [2][64][8];
__device__ unsigned g_rzflag[2][64][8];
__device__ unsigned g_bar_count[2];
__device__ unsigned g_bar_gen[2];

// ---------------- helpers ----------------------------------------------------
__device__ __forceinline__ uint32_t smem_u32(const void* p) {
    uint32_t a;
    asm("{ .reg .u64 t; cvta.to.shared.u64 t, %1; cvt.u32.u64 %0, t; }"
        : "=r"(a) : "l"(p));
    return a;
}
__device__ __forceinline__ void mmabf(float* d, const uint32_t* a,
                                      uint32_t b0, uint32_t b1) {
    asm volatile("mma.sync.aligned.m16n8k16.row.col.f32.bf16.bf16.f32 "
                 "{%0,%1,%2,%3},{%4,%5,%6,%7},{%8,%9},{%0,%1,%2,%3};"
                 : "+f"(d[0]), "+f"(d[1]), "+f"(d[2]), "+f"(d[3])
                 : "r"(a[0]), "r"(a[1]), "r"(a[2]), "r"(a[3]), "r"(b0), "r"(b1));
}
__device__ __forceinline__ uint32_t pk(float a, float b) {
    __nv_bfloat16 l = __float2bfloat16(a), h = __float2bfloat16(b);
    unsigned short ls = *(unsigned short*)&l, hs = *(unsigned short*)&h;
    return (uint32_t)ls | ((uint32_t)hs << 16);
}
__device__ __forceinline__ float bhi(float x) {
    return __bfloat162float(__float2bfloat16(x));
}
__device__ __forceinline__ void stcg_u32(unsigned* p, unsigned v) {
    asm volatile("st.global.cg.u32 [%0], %1;" :: "l"(p), "r"(v) : "memory");
}
// MORALLY-STRONG flag ops (proven in R16).
__device__ __forceinline__ unsigned ldacq_u32(const unsigned* p) {
    unsigned v;
    asm volatile("ld.acquire.gpu.global.u32 %0, [%1];" : "=r"(v) : "l"(p) : "memory");
    return v;
}
__device__ __forceinline__ void publish_flag(unsigned* slot, unsigned val) {
    asm volatile("st.release.gpu.global.u32 [%0], %1;" :: "l"(slot), "r"(val) : "memory");
}
// wait on all 64 flags (phase-1 needs every CTA's h chunk)
__device__ __forceinline__ void wait_flags(const unsigned (*flags)[8], int tid,
                                           unsigned tgt) {
    if (tid < 32) {
        const unsigned* f0 = &flags[tid][0];
        const unsigned* f1 = &flags[tid + 32][0];
        while (ldacq_u32(f0) < tgt) { }
        while (ldacq_u32(f1) < tgt) { }
    }
    __syncthreads();
}
// phase-2 wait: 32 R-CTA flags + the single Z-CTA flag (32 + c/2)
__device__ __forceinline__ void wait_flags_rz(const unsigned (*flags)[8], int tid,
                                              int c, unsigned tgt) {
    if (tid < 32) {
        const unsigned* f0 = &flags[tid][0];
        while (ldacq_u32(f0) < tgt) { }
        if (tid == 0) {
            const unsigned* fz = &flags[32 + (c >> 1)][0];
            while (ldacq_u32(fz) < tgt) { }
        }
    }
    __syncthreads();
}
// atomic rendezvous — used ONLY twice at end of run (flag reset)
__device__ __forceinline__ void dir_barrier(int dir) {
    __syncthreads();
    if (threadIdx.x == 0) {
        volatile unsigned* vgen = (volatile unsigned*)&g_bar_gen[dir];
        unsigned my = *vgen;
        __threadfence();
        unsigned a = atomicAdd(&g_bar_count[dir], 1u);
        if (a == NCTA_DIR - 1) {
            g_bar_count[dir] = 0;
            __threadfence();
            atomicAdd(&g_bar_gen[dir], 1u);
        } else {
            while (*vgen == my) { }
            __threadfence();
        }
    }
    __syncthreads();
}

// ---------------- weight-fragment prep for inproj (unchanged) ----------------
__global__ void __launch_bounds__(256) wprep_kernel(
    const float* __restrict__ Wr_f, const float* __restrict__ Wz_f, const float* __restrict__ Wh_f,
    const float* __restrict__ Wr_b, const float* __restrict__ Wz_b, const float* __restrict__ Wh_b)
{
    const int gate = blockIdx.y, dir = blockIdx.z;
    const float* W;
    if (dir == 0) W = (gate == 0) ? Wr_f : (gate == 1) ? Wz_f : Wh_f;
    else          W = (gate == 0) ? Wr_b : (gate == 1) ? Wz_b : Wh_b;

    int e = blockIdx.x * 256 + threadIdx.x;
    int lane = e & 31, q = (e >> 5) & 31, nt = e >> 10;
    int ge = lane >> 2, te = lane & 3;
    int j = nt * 8 + ge;
    uint32_t fr[4];
    #pragma unroll
    for (int breg = 0; breg < 2; ++breg) {
        int k0 = q * 16 + breg * 8 + 2 * te;
        float f0 = W[k0 * HH + j], f1 = W[(k0 + 1) * HH + j];
        fr[breg]     = pk(bhi(f0), bhi(f1));
        fr[2 + breg] = pk(f0 - bhi(f0), f1 - bhi(f1));
    }
    g_Wf[dir][gate][nt][q][lane] = make_uint4(fr[0], fr[1], fr[2], fr[3]);
}

// ---------------- inproj on tensor cores (unchanged from R12) ----------------
__global__ void __launch_bounds__(256) inproj_mma_kernel(
    const float* __restrict__ x,
    const float* __restrict__ br_f, const float* __restrict__ bz_f, const float* __restrict__ bh_f,
    const float* __restrict__ br_b, const float* __restrict__ bz_b, const float* __restrict__ bh_b)
{
    __shared__ char xs0[128 * 144];
    __shared__ char xs1[128 * 144];
    const uint32_t s0 = smem_u32(xs0), s1 = smem_u32(xs1);

    const int mTile = blockIdx.x, cTile = blockIdx.y, dir = blockIdx.z;
    const int tid = threadIdx.x, w = tid >> 5, lane = tid & 31;
    const int gid = lane >> 2, tig = lane & 3;
    const int wm = w >> 1, wn = w & 1;

    const float* bias[3] = { dir ? br_b : br_f, dir ? bz_b : bz_f, dir ? bh_b : bh_f };

    float C[3][2][2][4];
    #pragma unroll
    for (int g = 0; g < 3; ++g)
        #pragma unroll
        for (int mt = 0; mt < 2; ++mt)
            #pragma unroll
            for (int nt = 0; nt < 2; ++nt)
                #pragma unroll
                for (int i = 0; i < 4; ++i) C[g][mt][nt][i] = 0.f;

    const float* xb = x + (size_t)(mTile * 128) * II;

    #pragma unroll 1
    for (int kb = 0; kb < 8; ++kb) {
        __syncthreads();
        #pragma unroll
        for (int u = 0; u < 8; ++u) {
            int e = tid + 256 * u;
            int row = e >> 4, q4 = e & 15;
            float4 v = *(const float4*)(xb + row * II + kb * 64 + q4 * 4);
            *(uint2*)(xs0 + row * 144 + q4 * 8) =
                make_uint2(pk(bhi(v.x), bhi(v.y)), pk(bhi(v.z), bhi(v.w)));
            *(uint2*)(xs1 + row * 144 + q4 * 8) =
                make_uint2(pk(v.x - bhi(v.x), v.y - bhi(v.y)),
                           pk(v.z - bhi(v.z), v.w - bhi(v.w)));
        }
        __syncthreads();
        #pragma unroll
        for (int ks = 0; ks < 4; ++ks) {
            uint32_t a0[2][4], a1[2][4];
            #pragma unroll
            for (int mt = 0; mt < 2; ++mt) {
                uint32_t ao = (uint32_t)((wm * 32 + mt * 16 + (lane & 15)) * 144
                                         + (lane >> 4) * 16 + ks * 32);
                asm volatile("ldmatrix.sync.aligned.m8n8.x4.shared.b16 {%0,%1,%2,%3}, [%4];"
                             : "=r"(a0[mt][0]), "=r"(a0[mt][1]), "=r"(a0[mt][2]), "=r"(a0[mt][3])
                             : "r"(s0 + ao));
                asm volatile("ldmatrix.sync.aligned.m8n8.x4.shared.b16 {%0,%1,%2,%3}, [%4];"
                             : "=r"(a1[mt][0]), "=r"(a1[mt][1]), "=r"(a1[mt][2]), "=r"(a1[mt][3])
                             : "r"(s1 + ao));
            }
            #pragma unroll
            for (int g = 0; g < 3; ++g) {
                #pragma unroll
                for (int nt = 0; nt < 2; ++nt) {
                    uint4 bb = g_Wf[dir][g][cTile * 4 + wn * 2 + nt][kb * 4 + ks][lane];
                    #pragma unroll
                    for (int mt = 0; mt < 2; ++mt) {
                        mmabf(C[g][mt][nt], a0[mt], bb.x, bb.y);
                        mmabf(C[g][mt][nt], a1[mt], bb.x, bb.y);
                        mmabf(C[g][mt][nt], a0[mt], bb.z, bb.w);
                    }
                }
            }
        }
    }
    #pragma unroll
    for (int g = 0; g < 3; ++g)
        #pragma unroll
        for (int mt = 0; mt < 2; ++mt)
            #pragma unroll
            for (int nt = 0; nt < 2; ++nt)
                #pragma unroll
                for (int i = 0; i < 4; ++i) {
                    int row = mTile * 128 + wm * 32 + mt * 16 + gid + (i >> 1) * 8;
                    int j   = cTile * 32 + wn * 16 + nt * 8 + 2 * tig + (i & 1);
                    int b = row >> 9, t = row & (TT - 1);
                    float v = C[g][mt][nt][i] + bias[g][j];
                    if (g == 0)      g_Xrz[dir][t][b][j]      = v;
                    else if (g == 1) g_Xrz[dir][t][b][HH + j] = v;
                    else             g_Xh [dir][t][b][j]      = v;
                }
}

// ---------------- persistent dataflow recurrence ------------------------------
// Flags 0 at entry (reset at exit): init h-flag=1; step s: rz=1+s, h=2+s.
// A-operand loads are L1-CACHED (plain ld): the acquire in wait_flags orders
// them, and the 4x n1-warp redundancy is served by L1 instead of L2.
#define SM_BF1 0
#define SM_BF2 131072
#define SM_RED 196608
#define SM_BYTES 200704

__global__ void __launch_bounds__(512) gru_rec_kernel(
    const float* __restrict__ hf0, const float* __restrict__ hb0,
    const float* __restrict__ Whr_f, const float* __restrict__ Whz_f, const float* __restrict__ Whh_f,
    const float* __restrict__ Whr_b, const float* __restrict__ Whz_b, const float* __restrict__ Whh_b,
    float* __restrict__ out)
{
    extern __shared__ char smc[];
    uint32_t* Bf1 = (uint32_t*)(smc + SM_BF1);
    uint32_t* Bf2 = (uint32_t*)(smc + SM_BF2);
    float* red = (float*)(smc + SM_RED);

    const int tid = threadIdx.x;
    const int w = tid >> 5, lane = tid & 31;
    const int gid = lane >> 2, tig = lane & 3;
    const int dir = blockIdx.x >> 6;
    const int c   = blockIdx.x & 63;
    const bool isR = (c < 32);

    const float* __restrict__ Whr = dir ? Whr_b : Whr_f;
    const float* __restrict__ Whz = dir ? Whz_b : Whz_f;
    const float* __restrict__ Whh = dir ? Whh_b : Whh_f;
    const float* __restrict__ h0in = dir ? hb0 : hf0;
    const float* __restrict__ Wg  = isR ? Whr : Whz;

    // ---- one-time: recurrent weight splits into B-fragment SMEM ----
    for (int e = tid; e < 8192; e += 512) {
        int le = e & 31, q = (e >> 5) & 63, n = e >> 11;
        int ge = le >> 2, te = le & 3;
        int jw = (c * 32 + n * 8 + ge) & (HH - 1);
        #pragma unroll
        for (int breg = 0; breg < 2; ++breg) {
            int k0 = q * 16 + breg * 8 + 2 * te;
            float f0 = Wg[k0 * HH + jw], f1 = Wg[(k0 + 1) * HH + jw];
            Bf1[e * 4 + breg]     = pk(bhi(f0), bhi(f1));
            Bf1[e * 4 + 2 + breg] = pk(f0 - bhi(f0), f1 - bhi(f1));
        }
    }
    for (int e = tid; e < 4096; e += 512) {
        int le = e & 31, q = (e >> 5) & 63, n = (e >> 11) & 1;
        int ge = le >> 2, te = le & 3;
        int j2w = c * 16 + n * 8 + ge;
        #pragma unroll
        for (int breg = 0; breg < 2; ++breg) {
            int k0 = q * 16 + breg * 8 + 2 * te;
            float f0 = Whh[k0 * HH + j2w], f1 = Whh[(k0 + 1) * HH + j2w];
            Bf2[e * 4 + breg]     = pk(bhi(f0), bhi(f1));
            Bf2[e * 4 + 2 + breg] = pk(f0 - bhi(f0), f1 - bhi(f1));
        }
    }

    // ---- init: publish ONLY this CTA's h chunk (cols c*16 .. c*16+15) ----
    for (int e = tid; e < 1024; e += 512) {
        int row = e >> 4, col = c * 16 + (e & 15);
        float v = h0in[row * HH + col];
        asm volatile("st.global.cg.f32 [%0], %1;"
                     :: "l"(&g_hm[0][dir][row][col]), "f"(v) : "memory");
    }
    if (tid < 256) {
        int le = tid & 31, s = (tid >> 5) & 1, m = tid >> 6;
        uint32_t wds[4];
        #pragma unroll
        for (int r = 0; r < 4; ++r) {
            int row = m * 16 + (le >> 2) + 8 * (r & 1);
            int col = c * 16 + 2 * (le & 3) + 8 * (r >> 1);
            float v0 = h0in[row * HH + col], v1 = h0in[row * HH + col + 1];
            wds[r] = s ? pk(v0 - bhi(v0), v1 - bhi(v1)) : pk(v0, v1);
        }
        asm volatile("st.global.cg.v4.u32 [%0], {%1,%2,%3,%4};"
                     :: "l"(&g_hf[0][dir][m][c][s][tid & 31]),
                        "r"(wds[0]), "r"(wds[1]), "r"(wds[2]), "r"(wds[3]) : "memory");
    }
    __syncthreads();
    if (tid == 0) publish_flag(&g_hflag[dir][c][0], 1u);

    const int m1 = w >> 2, n1 = w & 3;          // phase1: 4M x 4N, full K
    const int wk = w >> 3, w8 = w & 7;          // phase2: 4M x 2N x 2K-split
    const int m2 = w8 >> 1, n2 = w8 & 1;

    for (int step = 0; step < TT; ++step) {
        const int t = dir ? (TT - 1 - step) : step;
        const int pcur = step & 1, pnxt = (step + 1) & 1;

        // ============ phase 1: wait h[step], GEMM, publish R/Z ============
        wait_flags(g_hflag[dir], tid, 1u + step);

        float A0[4] = {0,0,0,0}, A1[4] = {0,0,0,0}, A2[4] = {0,0,0,0};
        #pragma unroll 1
        for (int qb = 0; qb < 8; ++qb) {
            #pragma unroll
            for (int qi = 0; qi < 8; ++qi) {
                const int q = qb * 8 + qi;
                uint4 s0 = g_hf[pcur][dir][m1][q][0][lane];   // L1-cached
                uint4 s1 = g_hf[pcur][dir][m1][q][1][lane];
                uint4 bb = *(const uint4*)&Bf1[((n1 * 64 + q) * 32 + lane) * 4];
                mmabf(A0, (const uint32_t*)&s0, bb.x, bb.y);
                mmabf(A1, (const uint32_t*)&s1, bb.x, bb.y);
                mmabf(A2, (const uint32_t*)&s0, bb.z, bb.w);
            }
        }
        {
            const float* __restrict__ xrz = &g_Xrz[dir][t][0][0];
            float v[4];
            #pragma unroll
            for (int i = 0; i < 4; ++i) {
                int b  = m1 * 16 + gid + (i >> 1) * 8;
                int cc = n1 * 8 + 2 * tig + (i & 1);
                int jj = c * 32 + cc;
                float pre = A0[i] + A1[i] + A2[i] + xrz[b * (2 * HH) + jj];
                float s = 1.f / (1.f + __expf(-pre));
                if (isR) v[i] = s * g_hm[pcur][dir][b][jj];   // L1-cached
                else {
                    asm volatile("st.global.cg.f32 [%0], %1;"
                                 :: "l"(&g_Z[dir][b][jj - HH]), "f"(s) : "memory");
                }
            }
            if (isR) {
                int q = c * 2 + (n1 >> 1);
                int off = (n1 & 1) * 8;
                uint2 u0 = make_uint2(pk(v[0], v[1]), pk(v[2], v[3]));
                uint2 u1 = make_uint2(pk(v[0] - bhi(v[0]), v[1] - bhi(v[1])),
                                      pk(v[2] - bhi(v[2]), v[3] - bhi(v[3])));
                asm volatile("st.global.cg.v2.u32 [%0], {%1,%2};"
                             :: "l"((char*)&g_Rf[dir][m1][q][0][lane] + off),
                                "r"(u0.x), "r"(u0.y) : "memory");
                asm volatile("st.global.cg.v2.u32 [%0], {%1,%2};"
                             :: "l"((char*)&g_Rf[dir][m1][q][1][lane] + off),
                                "r"(u1.x), "r"(u1.y) : "memory");
            }
        }
        __syncthreads();
        if (tid == 0) publish_flag(&g_rzflag[dir][c][0], 1u + step);

        // ============ phase 2: wait R/Z[step], GEMM, publish h[step+1] ====
        wait_flags_rz(g_rzflag[dir], tid, c, 1u + step);

        float C0[4] = {0,0,0,0}, C1[4] = {0,0,0,0}, C2[4] = {0,0,0,0};
        #pragma unroll 1
        for (int qb = 0; qb < 4; ++qb) {
            #pragma unroll
            for (int qi = 0; qi < 8; ++qi) {
                const int q = wk * 32 + qb * 8 + qi;
                uint4 s0 = g_Rf[dir][m2][q][0][lane];         // L1-cached
                uint4 s1 = g_Rf[dir][m2][q][1][lane];
                uint4 bb = *(const uint4*)&Bf2[((n2 * 64 + q) * 32 + lane) * 4];
                mmabf(C0, (const uint32_t*)&s0, bb.x, bb.y);
                mmabf(C1, (const uint32_t*)&s1, bb.x, bb.y);
                mmabf(C2, (const uint32_t*)&s0, bb.z, bb.w);
            }
        }
        __syncthreads();
        if (wk == 1) {
            #pragma unroll
            for (int i = 0; i < 4; ++i) {
                int r  = m2 * 16 + gid + (i >> 1) * 8;
                int cc = n2 * 8 + 2 * tig + (i & 1);
                red[r * 16 + cc] = C0[i] + C1[i] + C2[i];
            }
        }
        __syncthreads();
        if (wk == 0) {
            const float* __restrict__ xh = &g_Xh[dir][t][0][0];
            float hn[4];
            #pragma unroll
            for (int i = 0; i < 4; ++i) {
                int b  = m2 * 16 + gid + (i >> 1) * 8;
                int cc = n2 * 8 + 2 * tig + (i & 1);
                int j2 = c * 16 + cc;
                float sum = C0[i] + C1[i] + C2[i] + red[b * 16 + cc];
                float htil = tanhf(sum + xh[b * HH + j2]);
                float z    = g_Z[dir][b][j2];                 // L1-cached
                float hold = g_hm[pcur][dir][b][j2];          // L1-cached
                float hnew = z * htil + (1.f - z) * hold;
                asm volatile("st.global.cg.f32 [%0], %1;"
                             :: "l"(&g_hm[pnxt][dir][b][j2]), "f"(hnew) : "memory");
                out[(size_t)(b * TT + t) * (2 * HH) + dir * HH + j2] = hnew;
                hn[i] = hnew;
            }
            int off = n2 * 8;
            uint2 u0 = make_uint2(pk(hn[0], hn[1]), pk(hn[2], hn[3]));
            uint2 u1 = make_uint2(pk(hn[0] - bhi(hn[0]), hn[1] - bhi(hn[1])),
                                  pk(hn[2] - bhi(hn[2]), hn[3] - bhi(hn[3])));
            asm volatile("st.global.cg.v2.u32 [%0], {%1,%2};"
                         :: "l"((char*)&g_hf[pnxt][dir][m2][c][0][lane] + off),
                            "r"(u0.x), "r"(u0.y) : "memory");
            asm volatile("st.global.cg.v2.u32 [%0], {%1,%2};"
                         :: "l"((char*)&g_hf[pnxt][dir][m2][c][1][lane] + off),
                            "r"(u1.x), "r"(u1.y) : "memory");
        }
        __syncthreads();
        if (tid == 0) publish_flag(&g_hflag[dir][c][0], 2u + step);
    }

    // ---- end of run: rendezvous (nobody still polls), reset flags to 0 ----
    dir_barrier(dir);
    if (tid == 0) {
        stcg_u32(&g_hflag [dir][c][0], 0u);
        stcg_u32(&g_rzflag[dir][c][0], 0u);
    }
    dir_barrier(dir);
}

// ---------------------------------------------------------------------------
extern "C" void kernel_launch(void* const* d_in, const int* in_sizes, int n_in,
                              void* d_out, int out_size) {
    (void)in_sizes; (void)n_in; (void)out_size;
    const float* x     = (const float*)d_in[0];
    const float* hf0   = (const float*)d_in[1];
    const float* hb0   = (const float*)d_in[2];
    const float* Whr_f = (const float*)d_in[3];
    const float* Wxr_f = (const float*)d_in[4];
    const float* br_f  = (const float*)d_in[5];
    const float* Whz_f = (const float*)d_in[6];
    const float* Wxz_f = (const float*)d_in[7];
    const float* bz_f  = (const float*)d_in[8];
    const float* Whh_f = (const float*)d_in[9];
    const float* Wxh_f = (const float*)d_in[10];
    const float* bh_f  = (const float*)d_in[11];
    const float* Whr_b = (const float*)d_in[12];
    const float* Wxr_b = (const float*)d_in[13];
    const float* br_b  = (const float*)d_in[14];
    const float* Whz_b = (const float*)d_in[15];
    const float* Wxz_b = (const float*)d_in[16];
    const float* bz_b  = (const float*)d_in[17];
    const float* Whh_b = (const float*)d_in[18];
    const float* Wxh_b = (const float*)d_in[19];
    const float* bh_b  = (const float*)d_in[20];
    float* out = (float*)d_out;

    static int smem_set = 0;
    if (!smem_set) {
        cudaFuncSetAttribute(gru_rec_kernel,
                             cudaFuncAttributeMaxDynamicSharedMemorySize,
                             SM_BYTES);
        smem_set = 1;
    }

    wprep_kernel<<<dim3(512, 3, 2), 256>>>(Wxr_f, Wxz_f, Wxh_f, Wxr_b, Wxz_b, Wxh_b);
    inproj_mma_kernel<<<dim3(256, 32, 2), 256>>>(x, br_f, bz_f, bh_f, br_b, bz_b, bh_b);
    gru_rec_kernel<<<2 * NCTA_DIR, 512, SM_BYTES>>>(hf0, hb0,
        Whr_f, Whz_f, Whh_f, Whr_b, Whz_b, Whh_b, out);
}